// round 7
// baseline (speedup 1.0000x reference)
#include <cuda_runtime.h>
#include <cuda_bf16.h>
#include <cstdint>

// out = ((3x+1)/4)^2 ; t = fma(0.75, x, 0.25), out = t*t
// 64M fp32, HBM-streaming. 8x float4 per thread, loads front-batched
// (MLP_p1 = 8), .cg loads + .cs stores. Exact-size fast kernel + scalar
// fallback for any residual elements (none for 8192x8192).

__global__ __launch_bounds__(256) void ewise_sq8_kernel(
    const float4* __restrict__ in, float4* __restrict__ out)
{
    const unsigned base = blockIdx.x * (256u * 8u) + threadIdx.x;
    const unsigned s = 256u;

    // Front-batch all 8 loads -> 8 outstanding LDG.128 per thread.
    float4 a0 = __ldcg(&in[base]);
    float4 a1 = __ldcg(&in[base + s]);
    float4 a2 = __ldcg(&in[base + 2u * s]);
    float4 a3 = __ldcg(&in[base + 3u * s]);
    float4 a4 = __ldcg(&in[base + 4u * s]);
    float4 a5 = __ldcg(&in[base + 5u * s]);
    float4 a6 = __ldcg(&in[base + 6u * s]);
    float4 a7 = __ldcg(&in[base + 7u * s]);

    #define EW(dst, src) do {                       \
        float t0 = fmaf(0.75f, (src).x, 0.25f);     \
        float t1 = fmaf(0.75f, (src).y, 0.25f);     \
        float t2 = fmaf(0.75f, (src).z, 0.25f);     \
        float t3 = fmaf(0.75f, (src).w, 0.25f);     \
        (dst).x = t0 * t0; (dst).y = t1 * t1;       \
        (dst).z = t2 * t2; (dst).w = t3 * t3;       \
    } while (0)

    float4 r0, r1, r2, r3, r4, r5, r6, r7;
    EW(r0, a0); EW(r1, a1); EW(r2, a2); EW(r3, a3);
    EW(r4, a4); EW(r5, a5); EW(r6, a6); EW(r7, a7);
    #undef EW

    __stcs(&out[base],          r0);
    __stcs(&out[base + s],      r1);
    __stcs(&out[base + 2u * s], r2);
    __stcs(&out[base + 3u * s], r3);
    __stcs(&out[base + 4u * s], r4);
    __stcs(&out[base + 5u * s], r5);
    __stcs(&out[base + 6u * s], r6);
    __stcs(&out[base + 7u * s], r7);
}

// Scalar tail kernel for elements not covered by the vector kernel.
__global__ void ewise_sq_tail_kernel(const float* __restrict__ in,
                                     float* __restrict__ out,
                                     unsigned start, unsigned n)
{
    unsigned i = start + blockIdx.x * blockDim.x + threadIdx.x;
    if (i < n) {
        float t = fmaf(0.75f, in[i], 0.25f);
        out[i] = t * t;
    }
}

extern "C" void kernel_launch(void* const* d_in, const int* in_sizes, int n_in,
                              void* d_out, int out_size)
{
    const float* x = (const float*)d_in[0];
    float* y = (float*)d_out;
    unsigned n = (unsigned)in_sizes[0];   // 67108864 for this problem

    const unsigned per_block_elems = 256u * 8u * 4u;   // 8192 fp32 per block
    unsigned full_blocks = n / per_block_elems;        // 8192 blocks (exact)
    unsigned covered = full_blocks * per_block_elems;

    if (full_blocks > 0) {
        ewise_sq8_kernel<<<full_blocks, 256>>>((const float4*)x, (float4*)y);
    }
    if (covered < n) {
        unsigned rem = n - covered;
        unsigned blocks = (rem + 255u) / 256u;
        ewise_sq_tail_kernel<<<blocks, 256>>>(x, y, covered, n);
    }
}

// round 11
// speedup vs baseline: 1.0055x; 1.0055x over previous
#include <cuda_runtime.h>
#include <cuda_bf16.h>
#include <cstdint>

// out = ((3x+1)/4)^2 ; t = fma(0.75, x, 0.25), out = t*t
// 64M fp32, HBM-streaming at the controller ceiling (~6.45 TB/s measured).
// 4x float4 per thread, front-batched last-use loads, .cs stores,
// 512-thread CTAs, exact-size fast path + scalar tail for generality.

__global__ __launch_bounds__(512) void ewise_sq4_kernel(
    const float4* __restrict__ in, float4* __restrict__ out)
{
    const unsigned base = blockIdx.x * (512u * 4u) + threadIdx.x;
    const unsigned s = 512u;

    // Front-batch 4 loads -> 4 outstanding LDG.128 per thread (MLP saturating
    // point per R2-vs-R7 evidence). .lu = last-use, no L2 retention needed.
    float4 a0 = __ldlu(&in[base]);
    float4 a1 = __ldlu(&in[base + s]);
    float4 a2 = __ldlu(&in[base + 2u * s]);
    float4 a3 = __ldlu(&in[base + 3u * s]);

    #define EW(dst, src) do {                       \
        float t0 = fmaf(0.75f, (src).x, 0.25f);     \
        float t1 = fmaf(0.75f, (src).y, 0.25f);     \
        float t2 = fmaf(0.75f, (src).z, 0.25f);     \
        float t3 = fmaf(0.75f, (src).w, 0.25f);     \
        (dst).x = t0 * t0; (dst).y = t1 * t1;       \
        (dst).z = t2 * t2; (dst).w = t3 * t3;       \
    } while (0)

    float4 r0, r1, r2, r3;
    EW(r0, a0); EW(r1, a1); EW(r2, a2); EW(r3, a3);
    #undef EW

    __stcs(&out[base],          r0);
    __stcs(&out[base + s],      r1);
    __stcs(&out[base + 2u * s], r2);
    __stcs(&out[base + 3u * s], r3);
}

// Scalar tail kernel for sizes not divisible by the vector block footprint.
__global__ void ewise_sq_tail_kernel(const float* __restrict__ in,
                                     float* __restrict__ out,
                                     unsigned start, unsigned n)
{
    unsigned i = start + blockIdx.x * blockDim.x + threadIdx.x;
    if (i < n) {
        float t = fmaf(0.75f, in[i], 0.25f);
        out[i] = t * t;
    }
}

extern "C" void kernel_launch(void* const* d_in, const int* in_sizes, int n_in,
                              void* d_out, int out_size)
{
    const float* x = (const float*)d_in[0];
    float* y = (float*)d_out;
    unsigned n = (unsigned)in_sizes[0];   // 67108864 for this problem

    const unsigned per_block_elems = 512u * 4u * 4u;   // 8192 fp32 per block
    unsigned full_blocks = n / per_block_elems;        // 8192 blocks (exact)
    unsigned covered = full_blocks * per_block_elems;

    if (full_blocks > 0) {
        ewise_sq4_kernel<<<full_blocks, 512>>>((const float4*)x, (float4*)y);
    }
    if (covered < n) {
        unsigned rem = n - covered;
        unsigned blocks = (rem + 255u) / 256u;
        ewise_sq_tail_kernel<<<blocks, 256>>>(x, y, covered, n);
    }
}